// round 1
// baseline (speedup 1.0000x reference)
#include <cuda_runtime.h>

#define HDIM 2048
#define BM 128
#define BN 128
#define BK 16
#define LDSS 132      // BM + 4 pad, keeps float4 smem accesses 16B-aligned & low-conflict
#define NRED 2048

// Scratch (no allocs allowed): summed weight matrix, norm partials, scale scalar.
__device__ float  g_wsum[HDIM * HDIM];
__device__ double g_partials[NRED];
__device__ float  g_scale;

// ---------------------------------------------------------------------------
// W_sum = fixed_w + plastic_w  (elementwise, float4)
// ---------------------------------------------------------------------------
__global__ void wsum_kernel(const float* __restrict__ fw, const float* __restrict__ pw) {
    int i = blockIdx.x * blockDim.x + threadIdx.x;
    float4 a = ((const float4*)fw)[i];
    float4 b = ((const float4*)pw)[i];
    ((float4*)g_wsum)[i] = make_float4(a.x + b.x, a.y + b.y, a.z + b.z, a.w + b.w);
}

// ---------------------------------------------------------------------------
// GEMM1 (NT): C[m][n] = sum_k A[m][k] * Wsum[n][k] + bias[n]
// A = x [M, HDIM] row-major, Wsum [HDIM, HDIM] row-major, C [M, HDIM]
// ---------------------------------------------------------------------------
__global__ __launch_bounds__(256, 2)
void gemm1_kernel(const float* __restrict__ A,
                  const float* __restrict__ bias,
                  float* __restrict__ C) {
    __shared__ float As[BK][LDSS];
    __shared__ float Bs[BK][LDSS];
    const int tid = threadIdx.x;
    const float* Ab = A + (size_t)blockIdx.y * BM * HDIM;
    const float* Bb = g_wsum + (size_t)blockIdx.x * BN * HDIM;

    const int lrow = tid >> 2;          // 0..63
    const int lcol = (tid & 3) << 2;    // 0,4,8,12
    const int tr = tid >> 4;            // 0..15
    const int tc = tid & 15;            // 0..15

    float acc[8][8] = {};

    for (int k0 = 0; k0 < HDIM; k0 += BK) {
        #pragma unroll
        for (int r = 0; r < 2; r++) {
            int row = lrow + r * 64;
            float4 v = *(const float4*)(Ab + (size_t)row * HDIM + k0 + lcol);
            As[lcol + 0][row] = v.x; As[lcol + 1][row] = v.y;
            As[lcol + 2][row] = v.z; As[lcol + 3][row] = v.w;
            float4 w = *(const float4*)(Bb + (size_t)row * HDIM + k0 + lcol);
            Bs[lcol + 0][row] = w.x; Bs[lcol + 1][row] = w.y;
            Bs[lcol + 2][row] = w.z; Bs[lcol + 3][row] = w.w;
        }
        __syncthreads();
        #pragma unroll
        for (int kk = 0; kk < BK; kk++) {
            float a[8], b[8];
            *(float4*)&a[0] = *(const float4*)&As[kk][tr * 8];
            *(float4*)&a[4] = *(const float4*)&As[kk][tr * 8 + 4];
            *(float4*)&b[0] = *(const float4*)&Bs[kk][tc * 8];
            *(float4*)&b[4] = *(const float4*)&Bs[kk][tc * 8 + 4];
            #pragma unroll
            for (int i = 0; i < 8; i++)
                #pragma unroll
                for (int j = 0; j < 8; j++)
                    acc[i][j] = fmaf(a[i], b[j], acc[i][j]);
        }
        __syncthreads();
    }

    const int gc0 = blockIdx.x * BN + tc * 8;
    float bv[8];
    *(float4*)&bv[0] = *(const float4*)(bias + gc0);
    *(float4*)&bv[4] = *(const float4*)(bias + gc0 + 4);
    #pragma unroll
    for (int i = 0; i < 8; i++) {
        size_t gr = (size_t)blockIdx.y * BM + tr * 8 + i;
        float4 v0 = make_float4(acc[i][0] + bv[0], acc[i][1] + bv[1],
                                acc[i][2] + bv[2], acc[i][3] + bv[3]);
        float4 v1 = make_float4(acc[i][4] + bv[4], acc[i][5] + bv[5],
                                acc[i][6] + bv[6], acc[i][7] + bv[7]);
        *(float4*)(C + gr * HDIM + gc0)     = v0;
        *(float4*)(C + gr * HDIM + gc0 + 4) = v1;
    }
}

// ---------------------------------------------------------------------------
// GEMM2 (TN) + hebbian epilogue:
//   G[h][k] = sum_m X[m][h] * C[m][k]
//   Wout[h][k] = plastic[h][k] + (rate*strength/M) * G[h][k]
// ---------------------------------------------------------------------------
__global__ __launch_bounds__(256, 2)
void gemm2_kernel(const float* __restrict__ X, const float* __restrict__ C,
                  const float* __restrict__ plastic,
                  const float* __restrict__ rate, const float* __restrict__ strength,
                  float* __restrict__ Wout, int M) {
    __shared__ float Xs[BK][LDSS];
    __shared__ float Cs[BK][LDSS];
    const int tid = threadIdx.x;
    const int h0 = blockIdx.y * BM;
    const int n0 = blockIdx.x * BN;
    const int lrow = tid >> 5;           // 0..7
    const int lcol = (tid & 31) << 2;    // 0..124
    const int tr = tid >> 4;
    const int tc = tid & 15;

    float acc[8][8] = {};

    for (int m0 = 0; m0 < M; m0 += BK) {
        #pragma unroll
        for (int r = 0; r < 2; r++) {
            int row = lrow + r * 8;      // 0..15
            *(float4*)&Xs[row][lcol] =
                *(const float4*)(X + (size_t)(m0 + row) * HDIM + h0 + lcol);
            *(float4*)&Cs[row][lcol] =
                *(const float4*)(C + (size_t)(m0 + row) * HDIM + n0 + lcol);
        }
        __syncthreads();
        #pragma unroll
        for (int kk = 0; kk < BK; kk++) {
            float a[8], b[8];
            *(float4*)&a[0] = *(const float4*)&Xs[kk][tr * 8];
            *(float4*)&a[4] = *(const float4*)&Xs[kk][tr * 8 + 4];
            *(float4*)&b[0] = *(const float4*)&Cs[kk][tc * 8];
            *(float4*)&b[4] = *(const float4*)&Cs[kk][tc * 8 + 4];
            #pragma unroll
            for (int i = 0; i < 8; i++)
                #pragma unroll
                for (int j = 0; j < 8; j++)
                    acc[i][j] = fmaf(a[i], b[j], acc[i][j]);
        }
        __syncthreads();
    }

    const float factor = rate[0] * strength[0] / (float)M;
    #pragma unroll
    for (int i = 0; i < 8; i++) {
        size_t h = (size_t)h0 + tr * 8 + i;
        size_t base = h * HDIM + n0 + tc * 8;
        float4 p0 = *(const float4*)(plastic + base);
        float4 p1 = *(const float4*)(plastic + base + 4);
        float4 v0 = make_float4(p0.x + factor * acc[i][0], p0.y + factor * acc[i][1],
                                p0.z + factor * acc[i][2], p0.w + factor * acc[i][3]);
        float4 v1 = make_float4(p1.x + factor * acc[i][4], p1.y + factor * acc[i][5],
                                p1.z + factor * acc[i][6], p1.w + factor * acc[i][7]);
        *(float4*)(Wout + base)     = v0;
        *(float4*)(Wout + base + 4) = v1;
    }
}

// ---------------------------------------------------------------------------
// Norm: deterministic two-stage sum of squares (no float atomics)
// ---------------------------------------------------------------------------
__global__ void sumsq_kernel(const float* __restrict__ W) {
    __shared__ double sh[256];
    const int tid = threadIdx.x;
    const float4* W4 = (const float4*)W;
    const size_t total4 = (size_t)HDIM * HDIM / 4;
    double s = 0.0;
    for (size_t i = (size_t)blockIdx.x * 256 + tid; i < total4;
         i += (size_t)gridDim.x * 256) {
        float4 v = W4[i];
        s += (double)v.x * v.x + (double)v.y * v.y
           + (double)v.z * v.z + (double)v.w * v.w;
    }
    sh[tid] = s;
    __syncthreads();
    for (int off = 128; off > 0; off >>= 1) {
        if (tid < off) sh[tid] += sh[tid + off];
        __syncthreads();
    }
    if (tid == 0) g_partials[blockIdx.x] = sh[0];
}

__global__ void finalize_kernel() {
    __shared__ double sh[256];
    const int tid = threadIdx.x;
    double s = 0.0;
    for (int i = tid; i < NRED; i += 256) s += g_partials[i];
    sh[tid] = s;
    __syncthreads();
    for (int off = 128; off > 0; off >>= 1) {
        if (tid < off) sh[tid] += sh[tid + off];
        __syncthreads();
    }
    if (tid == 0) {
        double norm = sqrt(sh[0]);
        g_scale = (norm > 1.0) ? (float)(1.0 / norm) : 1.0f;
    }
}

__global__ void scale_kernel(float* __restrict__ W) {
    size_t i = (size_t)blockIdx.x * blockDim.x + threadIdx.x;
    const float s = g_scale;
    float4 v = ((float4*)W)[i];
    v.x *= s; v.y *= s; v.z *= s; v.w *= s;
    ((float4*)W)[i] = v;
}

// ---------------------------------------------------------------------------
extern "C" void kernel_launch(void* const* d_in, const int* in_sizes, int n_in,
                              void* d_out, int out_size) {
    const float* x    = (const float*)d_in[0];  // [B,S,H]
    const float* pw   = (const float*)d_in[1];  // [H,H]
    const float* rate = (const float*)d_in[2];  // [1]
    const float* fw   = (const float*)d_in[3];  // [H,H]
    const float* fb   = (const float*)d_in[4];  // [H]
    const float* hs   = (const float*)d_in[5];  // scalar

    const int M = in_sizes[0] / HDIM;           // 16384
    float* combined = (float*)d_out;
    float* neww     = (float*)d_out + (size_t)M * HDIM;

    wsum_kernel<<<HDIM * HDIM / 4 / 256, 256>>>(fw, pw);

    dim3 g1(HDIM / BN, M / BM);
    gemm1_kernel<<<g1, 256>>>(x, fb, combined);

    dim3 g2(HDIM / BN, HDIM / BM);
    gemm2_kernel<<<g2, 256>>>(x, combined, pw, rate, hs, neww, M);

    sumsq_kernel<<<NRED, 256>>>(neww);
    finalize_kernel<<<1, 256>>>();
    scale_kernel<<<HDIM * HDIM / 4 / 256, 256>>>(neww);
}

// round 3
// speedup vs baseline: 3.1430x; 3.1430x over previous
#include <cuda_runtime.h>
#include <cuda_bf16.h>
#include <cstdint>

#define HDIM  2048
#define MROWS 16384
#define BM    128
#define BN    128
#define BK    64
#define NSPLIT 4
#define NRED  2048

#define TILE_BYTES  (128 * 128)        // 16KB: 128 rows x 128B (64 bf16)
#define A_HI_OFF    0
#define A_LO_OFF    (TILE_BYTES)
#define B_HI_OFF    (2 * TILE_BYTES)
#define B_LO_OFF    (3 * TILE_BYTES)
#define STAGE_BYTES (4 * TILE_BYTES)   // 64KB
#define SMEM_DYN    (2 * STAGE_BYTES + 1024)

// ---------------- device scratch (no allocs allowed) ----------------
__device__ __nv_bfloat16 g_xhi [(size_t)MROWS * HDIM];
__device__ __nv_bfloat16 g_xlo [(size_t)MROWS * HDIM];
__device__ __nv_bfloat16 g_xthi[(size_t)MROWS * HDIM];   // x^T [H, M]
__device__ __nv_bfloat16 g_xtlo[(size_t)MROWS * HDIM];
__device__ __nv_bfloat16 g_whi [(size_t)HDIM * HDIM];
__device__ __nv_bfloat16 g_wlo [(size_t)HDIM * HDIM];
__device__ __nv_bfloat16 g_cthi[(size_t)MROWS * HDIM];   // combined^T [H, M]
__device__ __nv_bfloat16 g_ctlo[(size_t)MROWS * HDIM];
__device__ float  g_part[(size_t)NSPLIT * HDIM * HDIM];  // split-K partials
__device__ double g_partials[NRED];
__device__ float  g_scale;

// ---------------- PTX helpers (all baseline sm_80+ features) ----------------
__device__ __forceinline__ uint32_t smem_u32(const void* p) {
    uint32_t a;
    asm("{ .reg .u64 t; cvta.to.shared.u64 t, %1; cvt.u32.u64 %0, t; }" : "=r"(a) : "l"(p));
    return a;
}
__device__ __forceinline__ uint32_t sw128(uint32_t o) { return o ^ ((o >> 3) & 0x70); }

__device__ __forceinline__ void cpasync16(uint32_t d, const void* s) {
    asm volatile("cp.async.cg.shared.global [%0], [%1], 16;" :: "r"(d), "l"(s));
}
#define CP_COMMIT() asm volatile("cp.async.commit_group;" ::: "memory")
#define CP_WAIT1()  asm volatile("cp.async.wait_group 1;" ::: "memory")
#define CP_WAIT0()  asm volatile("cp.async.wait_group 0;" ::: "memory")

__device__ __forceinline__ void ldsm4(uint32_t* r, uint32_t addr) {
    asm volatile("ldmatrix.sync.aligned.m8n8.x4.shared.b16 {%0,%1,%2,%3}, [%4];"
                 : "=r"(r[0]), "=r"(r[1]), "=r"(r[2]), "=r"(r[3]) : "r"(addr));
}
__device__ __forceinline__ void mma16816(float* c, const uint32_t* a, const uint32_t* b) {
    asm volatile(
        "mma.sync.aligned.m16n8k16.row.col.f32.bf16.bf16.f32 "
        "{%0,%1,%2,%3}, {%4,%5,%6,%7}, {%8,%9}, {%0,%1,%2,%3};"
        : "+f"(c[0]), "+f"(c[1]), "+f"(c[2]), "+f"(c[3])
        : "r"(a[0]), "r"(a[1]), "r"(a[2]), "r"(a[3]), "r"(b[0]), "r"(b[1]));
}

// ---------------- split helpers ----------------
__device__ __forceinline__ void split1(float v, __nv_bfloat16& h, __nv_bfloat16& l) {
    h = __float2bfloat16(v);
    l = __float2bfloat16(v - __bfloat162float(h));
}

__global__ void xsplit_kernel(const float* __restrict__ x,
                              __nv_bfloat16* __restrict__ oh,
                              __nv_bfloat16* __restrict__ ol) {
    size_t i = (size_t)blockIdx.x * blockDim.x + threadIdx.x;   // float4 index
    float4 v = ((const float4*)x)[i];
    __nv_bfloat16 h0, h1, h2, h3, l0, l1, l2, l3;
    split1(v.x, h0, l0); split1(v.y, h1, l1); split1(v.z, h2, l2); split1(v.w, h3, l3);
    __nv_bfloat162* ph = (__nv_bfloat162*)oh + i * 2;
    __nv_bfloat162* pl = (__nv_bfloat162*)ol + i * 2;
    ph[0] = __halves2bfloat162(h0, h1); ph[1] = __halves2bfloat162(h2, h3);
    pl[0] = __halves2bfloat162(l0, l1); pl[1] = __halves2bfloat162(l2, l3);
}

__global__ void wsplit_kernel(const float* __restrict__ fw, const float* __restrict__ pw,
                              __nv_bfloat16* __restrict__ oh,
                              __nv_bfloat16* __restrict__ ol) {
    size_t i = (size_t)blockIdx.x * blockDim.x + threadIdx.x;
    float4 a = ((const float4*)fw)[i];
    float4 b = ((const float4*)pw)[i];
    float4 v = make_float4(a.x + b.x, a.y + b.y, a.z + b.z, a.w + b.w);
    __nv_bfloat16 h0, h1, h2, h3, l0, l1, l2, l3;
    split1(v.x, h0, l0); split1(v.y, h1, l1); split1(v.z, h2, l2); split1(v.w, h3, l3);
    __nv_bfloat162* ph = (__nv_bfloat162*)oh + i * 2;
    __nv_bfloat162* pl = (__nv_bfloat162*)ol + i * 2;
    ph[0] = __halves2bfloat162(h0, h1); ph[1] = __halves2bfloat162(h2, h3);
    pl[0] = __halves2bfloat162(l0, l1); pl[1] = __halves2bfloat162(l2, l3);
}

// in [R,C] fp32 -> out_hi/out_lo [C,R] bf16 (transpose + split)
__global__ void tsplit_kernel(const float* __restrict__ in,
                              __nv_bfloat16* __restrict__ oh,
                              __nv_bfloat16* __restrict__ ol, int R, int C) {
    __shared__ float t[32][33];
    int tid = threadIdx.x;                 // 256
    int r0 = blockIdx.y * 32, c0 = blockIdx.x * 32;
    int row = tid >> 3, seg = tid & 7;
    float4 v = *(const float4*)(in + (size_t)(r0 + row) * C + c0 + seg * 4);
    t[row][seg * 4 + 0] = v.x; t[row][seg * 4 + 1] = v.y;
    t[row][seg * 4 + 2] = v.z; t[row][seg * 4 + 3] = v.w;
    __syncthreads();
    int oc = row;
    int rs = seg * 4;
    float a0 = t[rs + 0][oc], a1 = t[rs + 1][oc], a2 = t[rs + 2][oc], a3 = t[rs + 3][oc];
    __nv_bfloat16 h0, h1, h2, h3, l0, l1, l2, l3;
    split1(a0, h0, l0); split1(a1, h1, l1); split1(a2, h2, l2); split1(a3, h3, l3);
    size_t ob = ((size_t)(c0 + oc) * R + r0 + rs) >> 1;
    __nv_bfloat162* ph = (__nv_bfloat162*)oh + ob;
    __nv_bfloat162* pl = (__nv_bfloat162*)ol + ob;
    ph[0] = __halves2bfloat162(h0, h1); ph[1] = __halves2bfloat162(h2, h3);
    pl[0] = __halves2bfloat162(l0, l1); pl[1] = __halves2bfloat162(l2, l3);
}

// ---------------- HMMA mainloop (3-product bf16 split) ----------------
// acc[4][4][4]: warp tile 64x32, D[m,n] = sum_k (Ahi+Alo)[m,k]*(Bhi+Blo)[n,k]
__device__ __forceinline__ void mm_loop(float acc[4][4][4],
    const __nv_bfloat16* __restrict__ Ahi, const __nv_bfloat16* __restrict__ Alo,
    const __nv_bfloat16* __restrict__ Bhi, const __nv_bfloat16* __restrict__ Blo,
    int lda, int ldb, int m0, int n0, int kbeg, int NC)
{
    extern __shared__ char dsm[];
    uint32_t raw = smem_u32(dsm);
    uint32_t sbase = (raw + 1023) & ~1023u;

    const int tid  = threadIdx.x;
    const int lane = tid & 31;
    const int wid  = tid >> 5;
    const int wm = (wid >> 2) * 64;
    const int wn = (wid & 3) * 32;

    // ldmatrix per-lane geometry
    const int arow  = wm + (lane & 15);
    const int akadd = (lane >> 4) << 3;
    const int nrow  = wn + (lane & 7) + ((lane >> 4) << 3);
    const int bkadd = ((lane >> 3) & 1) << 3;

    auto issue = [&](int c) {
        uint32_t sb = sbase + (uint32_t)(c & 1) * STAGE_BYTES;
        const int k0 = kbeg + c * BK;
        #pragma unroll
        for (int t = 0; t < 4; t++) {
            int seg = tid + t * 256;
            int r = seg >> 3, sc = seg & 7;
            uint32_t so = sw128((uint32_t)(r * 128 + sc * 16));
            size_t ga = (size_t)(m0 + r) * lda + k0 + sc * 8;
            size_t gb = (size_t)(n0 + r) * ldb + k0 + sc * 8;
            cpasync16(sb + A_HI_OFF + so, Ahi + ga);
            cpasync16(sb + A_LO_OFF + so, Alo + ga);
            cpasync16(sb + B_HI_OFF + so, Bhi + gb);
            cpasync16(sb + B_LO_OFF + so, Blo + gb);
        }
    };

    issue(0); CP_COMMIT();

    #pragma unroll 1
    for (int c = 0; c < NC; c++) {
        if (c + 1 < NC) { issue(c + 1); CP_COMMIT(); CP_WAIT1(); }
        else            { CP_WAIT0(); }
        __syncthreads();

        uint32_t st = sbase + (uint32_t)(c & 1) * STAGE_BYTES;
        #pragma unroll
        for (int ks = 0; ks < 4; ks++) {
            uint32_t ah[4][4], al[4][4], bh[4][2], bl[4][2];
            #pragma unroll
            for (int mi = 0; mi < 4; mi++) {
                uint32_t off = sw128((uint32_t)((arow + mi * 16) * 128 + (ks * 16 + akadd) * 2));
                ldsm4(ah[mi], st + A_HI_OFF + off);
                ldsm4(al[mi], st + A_LO_OFF + off);
            }
            #pragma unroll
            for (int ng = 0; ng < 2; ng++) {
                uint32_t off = sw128((uint32_t)((nrow + ng * 16) * 128 + (ks * 16 + bkadd) * 2));
                uint32_t q[4];
                ldsm4(q, st + B_HI_OFF + off);
                bh[2*ng][0] = q[0]; bh[2*ng][1] = q[1];
                bh[2*ng+1][0] = q[2]; bh[2*ng+1][1] = q[3];
                ldsm4(q, st + B_LO_OFF + off);
                bl[2*ng][0] = q[0]; bl[2*ng][1] = q[1];
                bl[2*ng+1][0] = q[2]; bl[2*ng+1][1] = q[3];
            }
            #pragma unroll
            for (int mi = 0; mi < 4; mi++)
                #pragma unroll
                for (int ni = 0; ni < 4; ni++) {
                    mma16816(acc[mi][ni], ah[mi], bh[ni]);
                    mma16816(acc[mi][ni], al[mi], bh[ni]);
                    mma16816(acc[mi][ni], ah[mi], bl[ni]);
                }
        }
        __syncthreads();
    }
}

// ---------------- GEMM1: combined = x @ Wsum^T + bias ----------------
__global__ __launch_bounds__(256, 1)
void gemm1_mma(const float* __restrict__ bias, float* __restrict__ Cout) {
    float acc[4][4][4];
    #pragma unroll
    for (int i = 0; i < 4; i++)
        #pragma unroll
        for (int j = 0; j < 4; j++)
            #pragma unroll
            for (int q = 0; q < 4; q++) acc[i][j][q] = 0.f;

    const int m0 = blockIdx.y * BM, n0 = blockIdx.x * BN;
    mm_loop(acc, g_xhi, g_xlo, g_whi, g_wlo, HDIM, HDIM, m0, n0, 0, HDIM / BK);

    const int lane = threadIdx.x & 31, wid = threadIdx.x >> 5;
    const int wm = (wid >> 2) * 64, wn = (wid & 3) * 32;
    const int rbase = m0 + wm + (lane >> 2);
    const int cbase = n0 + wn + (lane & 3) * 2;
    #pragma unroll
    for (int mi = 0; mi < 4; mi++)
        #pragma unroll
        for (int ni = 0; ni < 4; ni++) {
            int r = rbase + mi * 16, cc = cbase + ni * 8;
            float2 bv = *(const float2*)(bias + cc);
            *(float2*)(Cout + (size_t)r * HDIM + cc) =
                make_float2(acc[mi][ni][0] + bv.x, acc[mi][ni][1] + bv.y);
            *(float2*)(Cout + (size_t)(r + 8) * HDIM + cc) =
                make_float2(acc[mi][ni][2] + bv.x, acc[mi][ni][3] + bv.y);
        }
}

// ---------------- GEMM2 partial: P[s] = X^T @ C over k-split s ----------------
__global__ __launch_bounds__(256, 1)
void gemm2_mma(int M) {
    float acc[4][4][4];
    #pragma unroll
    for (int i = 0; i < 4; i++)
        #pragma unroll
        for (int j = 0; j < 4; j++)
            #pragma unroll
            for (int q = 0; q < 4; q++) acc[i][j][q] = 0.f;

    const int s = blockIdx.z;
    const int kper = M / NSPLIT;
    const int h0 = blockIdx.y * BM, n0 = blockIdx.x * BN;
    mm_loop(acc, g_xthi, g_xtlo, g_cthi, g_ctlo, M, M, h0, n0, s * kper, kper / BK);

    float* P = g_part + (size_t)s * HDIM * HDIM;
    const int lane = threadIdx.x & 31, wid = threadIdx.x >> 5;
    const int wm = (wid >> 2) * 64, wn = (wid & 3) * 32;
    const int rbase = h0 + wm + (lane >> 2);
    const int cbase = n0 + wn + (lane & 3) * 2;
    #pragma unroll
    for (int mi = 0; mi < 4; mi++)
        #pragma unroll
        for (int ni = 0; ni < 4; ni++) {
            int r = rbase + mi * 16, cc = cbase + ni * 8;
            *(float2*)(P + (size_t)r * HDIM + cc) =
                make_float2(acc[mi][ni][0], acc[mi][ni][1]);
            *(float2*)(P + (size_t)(r + 8) * HDIM + cc) =
                make_float2(acc[mi][ni][2], acc[mi][ni][3]);
        }
}

// ---------------- combine + norm + scale ----------------
__global__ void combine_kernel(const float* __restrict__ plastic,
                               const float* __restrict__ rate,
                               const float* __restrict__ hs,
                               float* __restrict__ Wout, float invM) {
    size_t i = (size_t)blockIdx.x * blockDim.x + threadIdx.x;   // float4 index
    const float factor = rate[0] * hs[0] * invM;
    const size_t stride4 = (size_t)HDIM * HDIM / 4;
    float4 s0 = ((const float4*)g_part)[i];
    float4 s1 = ((const float4*)g_part)[i + stride4];
    float4 s2 = ((const float4*)g_part)[i + 2 * stride4];
    float4 s3 = ((const float4*)g_part)[i + 3 * stride4];
    float4 p  = ((const float4*)plastic)[i];
    float4 o;
    o.x = p.x + factor * (s0.x + s1.x + s2.x + s3.x);
    o.y = p.y + factor * (s0.y + s1.y + s2.y + s3.y);
    o.z = p.z + factor * (s0.z + s1.z + s2.z + s3.z);
    o.w = p.w + factor * (s0.w + s1.w + s2.w + s3.w);
    ((float4*)Wout)[i] = o;
}

__global__ void sumsq_kernel(const float* __restrict__ W) {
    __shared__ double sh[256];
    const int tid = threadIdx.x;
    const float4* W4 = (const float4*)W;
    const size_t total4 = (size_t)HDIM * HDIM / 4;
    double s = 0.0;
    for (size_t i = (size_t)blockIdx.x * 256 + tid; i < total4;
         i += (size_t)gridDim.x * 256) {
        float4 v = W4[i];
        s += (double)v.x * v.x + (double)v.y * v.y
           + (double)v.z * v.z + (double)v.w * v.w;
    }
    sh[tid] = s;
    __syncthreads();
    for (int off = 128; off > 0; off >>= 1) {
        if (tid < off) sh[tid] += sh[tid + off];
        __syncthreads();
    }
    if (tid == 0) g_partials[blockIdx.x] = sh[0];
}

__global__ void finalize_kernel() {
    __shared__ double sh[256];
    const int tid = threadIdx.x;
    double s = 0.0;
    for (int i = tid; i < NRED; i += 256) s += g_partials[i];
    sh[tid] = s;
    __syncthreads();
    for (int off = 128; off > 0; off >>= 1) {
        if (tid < off) sh[tid] += sh[tid + off];
        __syncthreads();
    }
    if (tid == 0) {
        double norm = sqrt(sh[0]);
        g_scale = (norm > 1.0) ? (float)(1.0 / norm) : 1.0f;
    }
}

__global__ void scale_kernel(float* __restrict__ W) {
    size_t i = (size_t)blockIdx.x * blockDim.x + threadIdx.x;
    const float s = g_scale;
    float4 v = ((float4*)W)[i];
    v.x *= s; v.y *= s; v.z *= s; v.w *= s;
    ((float4*)W)[i] = v;
}

// ---------------- launch ----------------
extern "C" void kernel_launch(void* const* d_in, const int* in_sizes, int n_in,
                              void* d_out, int out_size) {
    const float* x    = (const float*)d_in[0];  // [M, H]
    const float* pw   = (const float*)d_in[1];  // [H, H]
    const float* rate = (const float*)d_in[2];  // [1]
    const float* fw   = (const float*)d_in[3];  // [H, H]
    const float* fb   = (const float*)d_in[4];  // [H]
    const float* hs   = (const float*)d_in[5];  // scalar

    const int M = in_sizes[0] / HDIM;           // 16384
    float* combined = (float*)d_out;
    float* neww     = (float*)d_out + (size_t)M * HDIM;

    static bool attr_done = false;
    if (!attr_done) {
        cudaFuncSetAttribute(gemm1_mma, cudaFuncAttributeMaxDynamicSharedMemorySize, SMEM_DYN);
        cudaFuncSetAttribute(gemm2_mma, cudaFuncAttributeMaxDynamicSharedMemorySize, SMEM_DYN);
        attr_done = true;
    }

    __nv_bfloat16 *xhi, *xlo, *xthi, *xtlo, *whi, *wlo, *cthi, *ctlo;
    cudaGetSymbolAddress((void**)&xhi,  g_xhi);
    cudaGetSymbolAddress((void**)&xlo,  g_xlo);
    cudaGetSymbolAddress((void**)&xthi, g_xthi);
    cudaGetSymbolAddress((void**)&xtlo, g_xtlo);
    cudaGetSymbolAddress((void**)&whi,  g_whi);
    cudaGetSymbolAddress((void**)&wlo,  g_wlo);
    cudaGetSymbolAddress((void**)&cthi, g_cthi);
    cudaGetSymbolAddress((void**)&ctlo, g_ctlo);

    // operand prep (split + transpose)
    wsplit_kernel<<<HDIM * HDIM / 4 / 256, 256>>>(fw, pw, whi, wlo);
    xsplit_kernel<<<(int)((size_t)M * HDIM / 4 / 256), 256>>>(x, xhi, xlo);
    {
        dim3 g(HDIM / 32, M / 32);
        tsplit_kernel<<<g, 256>>>(x, xthi, xtlo, M, HDIM);
    }

    // GEMM1
    {
        dim3 g(HDIM / BN, M / BM);
        gemm1_mma<<<g, 256, SMEM_DYN>>>(fb, combined);
    }

    // transpose+split combined -> [H, M]
    {
        dim3 g(HDIM / 32, M / 32);
        tsplit_kernel<<<g, 256>>>(combined, cthi, ctlo, M, HDIM);
    }

    // GEMM2 split-K partials, then deterministic combine
    {
        dim3 g(HDIM / BN, HDIM / BM, NSPLIT);
        gemm2_mma<<<g, 256, SMEM_DYN>>>(M);
    }
    combine_kernel<<<HDIM * HDIM / 4 / 256, 256>>>(pw, rate, hs, neww, 1.0f / (float)M);

    sumsq_kernel<<<NRED, 256>>>(neww);
    finalize_kernel<<<1, 256>>>();
    scale_kernel<<<HDIM * HDIM / 4 / 256, 256>>>(neww);
}

// round 5
// speedup vs baseline: 3.6007x; 1.1456x over previous
#include <cuda_runtime.h>
#include <cuda_bf16.h>
#include <cstdint>

#define HDIM  2048
#define MROWS 16384
#define BM    128
#define BN    128
#define BK    64
#define NSPLIT 4
#define NRED  2048

#define TILE_BYTES  (128 * 128)        // 16KB: 128 rows x 128B (64 bf16)
#define STAGE4      (4 * TILE_BYTES)   // gemm1 stage: Ahi Alo Bhi Blo
#define STAGE3      (3 * TILE_BYTES)   // gemm2 stage: Ahi Alo Bhi
#define SMEM1       (3 * STAGE4 + 1024)
#define SMEM2       (3 * STAGE3 + 1024)

// ---------------- device scratch (no allocs allowed) ----------------
__device__ __nv_bfloat16 g_xhi [(size_t)MROWS * HDIM];
__device__ __nv_bfloat16 g_xlo [(size_t)MROWS * HDIM];
__device__ __nv_bfloat16 g_xthi[(size_t)MROWS * HDIM];   // x^T [H, M]
__device__ __nv_bfloat16 g_xtlo[(size_t)MROWS * HDIM];
__device__ __nv_bfloat16 g_whi [(size_t)HDIM * HDIM];
__device__ __nv_bfloat16 g_wlo [(size_t)HDIM * HDIM];
__device__ __nv_bfloat16 g_cthi[(size_t)MROWS * HDIM];   // combined^T [H, M] (hi only)
__device__ float  g_part[(size_t)NSPLIT * HDIM * HDIM];  // split-K partials
__device__ double g_partials[NRED];
__device__ float  g_scale;

// ---------------- PTX helpers (baseline sm_80+ features only) ----------------
__device__ __forceinline__ uint32_t smem_u32(const void* p) {
    uint32_t a;
    asm("{ .reg .u64 t; cvta.to.shared.u64 t, %1; cvt.u32.u64 %0, t; }" : "=r"(a) : "l"(p));
    return a;
}
__device__ __forceinline__ uint32_t sw128(uint32_t o) { return o ^ ((o >> 3) & 0x70); }

__device__ __forceinline__ void cpasync16(uint32_t d, const void* s) {
    asm volatile("cp.async.cg.shared.global [%0], [%1], 16;" :: "r"(d), "l"(s));
}
#define CP_COMMIT() asm volatile("cp.async.commit_group;" ::: "memory")
#define CP_WAIT2()  asm volatile("cp.async.wait_group 2;" ::: "memory")
#define CP_WAIT1()  asm volatile("cp.async.wait_group 1;" ::: "memory")
#define CP_WAIT0()  asm volatile("cp.async.wait_group 0;" ::: "memory")

__device__ __forceinline__ void ldsm4(uint32_t* r, uint32_t addr) {
    asm volatile("ldmatrix.sync.aligned.m8n8.x4.shared.b16 {%0,%1,%2,%3}, [%4];"
                 : "=r"(r[0]), "=r"(r[1]), "=r"(r[2]), "=r"(r[3]) : "r"(addr));
}
__device__ __forceinline__ void mma16816(float* c, const uint32_t* a, const uint32_t* b) {
    asm volatile(
        "mma.sync.aligned.m16n8k16.row.col.f32.bf16.bf16.f32 "
        "{%0,%1,%2,%3}, {%4,%5,%6,%7}, {%8,%9}, {%0,%1,%2,%3};"
        : "+f"(c[0]), "+f"(c[1]), "+f"(c[2]), "+f"(c[3])
        : "r"(a[0]), "r"(a[1]), "r"(a[2]), "r"(a[3]), "r"(b[0]), "r"(b[1]));
}

// ---------------- split helpers ----------------
__device__ __forceinline__ void split1(float v, __nv_bfloat16& h, __nv_bfloat16& l) {
    h = __float2bfloat16(v);
    l = __float2bfloat16(v - __bfloat162float(h));
}

__global__ void xsplit_kernel(const float* __restrict__ x,
                              __nv_bfloat16* __restrict__ oh,
                              __nv_bfloat16* __restrict__ ol) {
    size_t i = (size_t)blockIdx.x * blockDim.x + threadIdx.x;   // float4 index
    float4 v = ((const float4*)x)[i];
    __nv_bfloat16 h0, h1, h2, h3, l0, l1, l2, l3;
    split1(v.x, h0, l0); split1(v.y, h1, l1); split1(v.z, h2, l2); split1(v.w, h3, l3);
    __nv_bfloat162* ph = (__nv_bfloat162*)oh + i * 2;
    __nv_bfloat162* pl = (__nv_bfloat162*)ol + i * 2;
    ph[0] = __halves2bfloat162(h0, h1); ph[1] = __halves2bfloat162(h2, h3);
    pl[0] = __halves2bfloat162(l0, l1); pl[1] = __halves2bfloat162(l2, l3);
}

__global__ void wsplit_kernel(const float* __restrict__ fw, const float* __restrict__ pw,
                              __nv_bfloat16* __restrict__ oh,
                              __nv_bfloat16* __restrict__ ol) {
    size_t i = (size_t)blockIdx.x * blockDim.x + threadIdx.x;
    float4 a = ((const float4*)fw)[i];
    float4 b = ((const float4*)pw)[i];
    float4 v = make_float4(a.x + b.x, a.y + b.y, a.z + b.z, a.w + b.w);
    __nv_bfloat16 h0, h1, h2, h3, l0, l1, l2, l3;
    split1(v.x, h0, l0); split1(v.y, h1, l1); split1(v.z, h2, l2); split1(v.w, h3, l3);
    __nv_bfloat162* ph = (__nv_bfloat162*)oh + i * 2;
    __nv_bfloat162* pl = (__nv_bfloat162*)ol + i * 2;
    ph[0] = __halves2bfloat162(h0, h1); ph[1] = __halves2bfloat162(h2, h3);
    pl[0] = __halves2bfloat162(l0, l1); pl[1] = __halves2bfloat162(l2, l3);
}

// in [R,C] fp32 -> out_hi/out_lo [C,R] bf16 (transpose + split)
__global__ void tsplit_kernel(const float* __restrict__ in,
                              __nv_bfloat16* __restrict__ oh,
                              __nv_bfloat16* __restrict__ ol, int R, int C) {
    __shared__ float t[32][33];
    int tid = threadIdx.x;                 // 256
    int r0 = blockIdx.y * 32, c0 = blockIdx.x * 32;
    int row = tid >> 3, seg = tid & 7;
    float4 v = *(const float4*)(in + (size_t)(r0 + row) * C + c0 + seg * 4);
    t[row][seg * 4 + 0] = v.x; t[row][seg * 4 + 1] = v.y;
    t[row][seg * 4 + 2] = v.z; t[row][seg * 4 + 3] = v.w;
    __syncthreads();
    int oc = row;
    int rs = seg * 4;
    float a0 = t[rs + 0][oc], a1 = t[rs + 1][oc], a2 = t[rs + 2][oc], a3 = t[rs + 3][oc];
    __nv_bfloat16 h0, h1, h2, h3, l0, l1, l2, l3;
    split1(a0, h0, l0); split1(a1, h1, l1); split1(a2, h2, l2); split1(a3, h3, l3);
    size_t ob = ((size_t)(c0 + oc) * R + r0 + rs) >> 1;
    __nv_bfloat162* ph = (__nv_bfloat162*)oh + ob;
    __nv_bfloat162* pl = (__nv_bfloat162*)ol + ob;
    ph[0] = __halves2bfloat162(h0, h1); ph[1] = __halves2bfloat162(h2, h3);
    pl[0] = __halves2bfloat162(l0, l1); pl[1] = __halves2bfloat162(l2, l3);
}

// transpose, hi only: in [R,C] fp32 -> out [C,R] bf16
__global__ void tsplit_hi_kernel(const float* __restrict__ in,
                                 __nv_bfloat16* __restrict__ oh, int R, int C) {
    __shared__ float t[32][33];
    int tid = threadIdx.x;
    int r0 = blockIdx.y * 32, c0 = blockIdx.x * 32;
    int row = tid >> 3, seg = tid & 7;
    float4 v = *(const float4*)(in + (size_t)(r0 + row) * C + c0 + seg * 4);
    t[row][seg * 4 + 0] = v.x; t[row][seg * 4 + 1] = v.y;
    t[row][seg * 4 + 2] = v.z; t[row][seg * 4 + 3] = v.w;
    __syncthreads();
    int oc = row;
    int rs = seg * 4;
    __nv_bfloat16 h0 = __float2bfloat16(t[rs + 0][oc]);
    __nv_bfloat16 h1 = __float2bfloat16(t[rs + 1][oc]);
    __nv_bfloat16 h2 = __float2bfloat16(t[rs + 2][oc]);
    __nv_bfloat16 h3 = __float2bfloat16(t[rs + 3][oc]);
    size_t ob = ((size_t)(c0 + oc) * R + r0 + rs) >> 1;
    __nv_bfloat162* ph = (__nv_bfloat162*)oh + ob;
    ph[0] = __halves2bfloat162(h0, h1); ph[1] = __halves2bfloat162(h2, h3);
}

// ---------------- HMMA mainloop, 3-stage cp.async pipeline ----------------
// BLO=true : 3 products (AhBh + AlBh + AhBl), stage = Ahi Alo Bhi Blo
// BLO=false: 2 products (AhBh + AlBh),        stage = Ahi Alo Bhi
template <bool BLO>
__device__ __forceinline__ void mm_loop(float acc[4][4][4],
    const __nv_bfloat16* __restrict__ Ahi, const __nv_bfloat16* __restrict__ Alo,
    const __nv_bfloat16* __restrict__ Bhi, const __nv_bfloat16* __restrict__ Blo,
    int lda, int ldb, int m0, int n0, int kbeg, int NC)
{
    constexpr uint32_t A_HI = 0;
    constexpr uint32_t A_LO = TILE_BYTES;
    constexpr uint32_t B_HI = 2 * TILE_BYTES;
    constexpr uint32_t B_LO = 3 * TILE_BYTES;
    constexpr uint32_t STG  = BLO ? STAGE4 : STAGE3;

    extern __shared__ char dsm[];
    uint32_t raw = smem_u32(dsm);
    uint32_t sbase = (raw + 1023) & ~1023u;

    const int tid  = threadIdx.x;
    const int lane = tid & 31;
    const int wid  = tid >> 5;
    const int wm = (wid >> 2) * 64;
    const int wn = (wid & 3) * 32;

    const int arow  = wm + (lane & 15);
    const int akadd = (lane >> 4) << 3;
    const int nrow  = wn + (lane & 7) + ((lane >> 4) << 3);
    const int bkadd = ((lane >> 3) & 1) << 3;

    auto issue = [&](int c) {
        uint32_t sb = sbase + (uint32_t)(c % 3) * STG;
        const int k0 = kbeg + c * BK;
        #pragma unroll
        for (int t = 0; t < 4; t++) {
            int seg = tid + t * 256;
            int r = seg >> 3, sc = seg & 7;
            uint32_t so = sw128((uint32_t)(r * 128 + sc * 16));
            size_t ga = (size_t)(m0 + r) * lda + k0 + sc * 8;
            size_t gb = (size_t)(n0 + r) * ldb + k0 + sc * 8;
            cpasync16(sb + A_HI + so, Ahi + ga);
            cpasync16(sb + A_LO + so, Alo + ga);
            cpasync16(sb + B_HI + so, Bhi + gb);
            if (BLO) cpasync16(sb + B_LO + so, Blo + gb);
        }
    };

    issue(0); CP_COMMIT();
    issue(1); CP_COMMIT();

    #pragma unroll 1
    for (int c = 0; c < NC; c++) {
        if (c + 2 < NC) { issue(c + 2); CP_COMMIT(); CP_WAIT2(); }
        else if (c + 1 < NC) { CP_WAIT1(); }
        else { CP_WAIT0(); }
        __syncthreads();

        uint32_t st = sbase + (uint32_t)(c % 3) * STG;
        #pragma unroll
        for (int ks = 0; ks < 4; ks++) {
            uint32_t ah[4][4], al[4][4], bh[4][2], bl[4][2];
            #pragma unroll
            for (int mi = 0; mi < 4; mi++) {
                uint32_t off = sw128((uint32_t)((arow + mi * 16) * 128 + (ks * 16 + akadd) * 2));
                ldsm4(ah[mi], st + A_HI + off);
                ldsm4(al[mi], st + A_LO + off);
            }
            #pragma unroll
            for (int ng = 0; ng < 2; ng++) {
                uint32_t off = sw128((uint32_t)((nrow + ng * 16) * 128 + (ks * 16 + bkadd) * 2));
                uint32_t q[4];
                ldsm4(q, st + B_HI + off);
                bh[2*ng][0] = q[0]; bh[2*ng][1] = q[1];
                bh[2*ng+1][0] = q[2]; bh[2*ng+1][1] = q[3];
                if (BLO) {
                    ldsm4(q, st + B_LO + off);
                    bl[2*ng][0] = q[0]; bl[2*ng][1] = q[1];
                    bl[2*ng+1][0] = q[2]; bl[2*ng+1][1] = q[3];
                }
            }
            #pragma unroll
            for (int mi = 0; mi < 4; mi++)
                #pragma unroll
                for (int ni = 0; ni < 4; ni++) {
                    mma16816(acc[mi][ni], ah[mi], bh[ni]);
                    mma16816(acc[mi][ni], al[mi], bh[ni]);
                    if (BLO) mma16816(acc[mi][ni], ah[mi], bl[ni]);
                }
        }
        __syncthreads();
    }
}

// ---------------- GEMM1: combined = x @ Wsum^T + bias ----------------
__global__ __launch_bounds__(256, 1)
void gemm1_mma(const float* __restrict__ bias, float* __restrict__ Cout) {
    float acc[4][4][4];
    #pragma unroll
    for (int i = 0; i < 4; i++)
        #pragma unroll
        for (int j = 0; j < 4; j++)
            #pragma unroll
            for (int q = 0; q < 4; q++) acc[i][j][q] = 0.f;

    const int m0 = blockIdx.y * BM, n0 = blockIdx.x * BN;
    mm_loop<true>(acc, g_xhi, g_xlo, g_whi, g_wlo, HDIM, HDIM, m0, n0, 0, HDIM / BK);

    const int lane = threadIdx.x & 31, wid = threadIdx.x >> 5;
    const int wm = (wid >> 2) * 64, wn = (wid & 3) * 32;
    const int rbase = m0 + wm + (lane >> 2);
    const int cbase = n0 + wn + (lane & 3) * 2;
    #pragma unroll
    for (int mi = 0; mi < 4; mi++)
        #pragma unroll
        for (int ni = 0; ni < 4; ni++) {
            int r = rbase + mi * 16, cc = cbase + ni * 8;
            float2 bv = *(const float2*)(bias + cc);
            *(float2*)(Cout + (size_t)r * HDIM + cc) =
                make_float2(acc[mi][ni][0] + bv.x, acc[mi][ni][1] + bv.y);
            *(float2*)(Cout + (size_t)(r + 8) * HDIM + cc) =
                make_float2(acc[mi][ni][2] + bv.x, acc[mi][ni][3] + bv.y);
        }
}

// ---------------- GEMM2 partial: P[s] = X^T @ C over k-split s (2-product) ----
__global__ __launch_bounds__(256, 1)
void gemm2_mma(int M) {
    float acc[4][4][4];
    #pragma unroll
    for (int i = 0; i < 4; i++)
        #pragma unroll
        for (int j = 0; j < 4; j++)
            #pragma unroll
            for (int q = 0; q < 4; q++) acc[i][j][q] = 0.f;

    const int s = blockIdx.z;
    const int kper = M / NSPLIT;
    const int h0 = blockIdx.y * BM, n0 = blockIdx.x * BN;
    mm_loop<false>(acc, g_xthi, g_xtlo, g_cthi, (const __nv_bfloat16*)0,
                   M, M, h0, n0, s * kper, kper / BK);

    float* P = g_part + (size_t)s * HDIM * HDIM;
    const int lane = threadIdx.x & 31, wid = threadIdx.x >> 5;
    const int wm = (wid >> 2) * 64, wn = (wid & 3) * 32;
    const int rbase = h0 + wm + (lane >> 2);
    const int cbase = n0 + wn + (lane & 3) * 2;
    #pragma unroll
    for (int mi = 0; mi < 4; mi++)
        #pragma unroll
        for (int ni = 0; ni < 4; ni++) {
            int r = rbase + mi * 16, cc = cbase + ni * 8;
            *(float2*)(P + (size_t)r * HDIM + cc) =
                make_float2(acc[mi][ni][0], acc[mi][ni][1]);
            *(float2*)(P + (size_t)(r + 8) * HDIM + cc) =
                make_float2(acc[mi][ni][2], acc[mi][ni][3]);
        }
}

// ---------------- combine + norm + scale ----------------
__global__ void combine_kernel(const float* __restrict__ plastic,
                               const float* __restrict__ rate,
                               const float* __restrict__ hs,
                               float* __restrict__ Wout, float invM) {
    size_t i = (size_t)blockIdx.x * blockDim.x + threadIdx.x;   // float4 index
    const float factor = rate[0] * hs[0] * invM;
    const size_t stride4 = (size_t)HDIM * HDIM / 4;
    float4 s0 = ((const float4*)g_part)[i];
    float4 s1 = ((const float4*)g_part)[i + stride4];
    float4 s2 = ((const float4*)g_part)[i + 2 * stride4];
    float4 s3 = ((const float4*)g_part)[i + 3 * stride4];
    float4 p  = ((const float4*)plastic)[i];
    float4 o;
    o.x = p.x + factor * (s0.x + s1.x + s2.x + s3.x);
    o.y = p.y + factor * (s0.y + s1.y + s2.y + s3.y);
    o.z = p.z + factor * (s0.z + s1.z + s2.z + s3.z);
    o.w = p.w + factor * (s0.w + s1.w + s2.w + s3.w);
    ((float4*)Wout)[i] = o;
}

__global__ void sumsq_kernel(const float* __restrict__ W) {
    __shared__ double sh[256];
    const int tid = threadIdx.x;
    const float4* W4 = (const float4*)W;
    const size_t total4 = (size_t)HDIM * HDIM / 4;
    double s = 0.0;
    for (size_t i = (size_t)blockIdx.x * 256 + tid; i < total4;
         i += (size_t)gridDim.x * 256) {
        float4 v = W4[i];
        s += (double)v.x * v.x + (double)v.y * v.y
           + (double)v.z * v.z + (double)v.w * v.w;
    }
    sh[tid] = s;
    __syncthreads();
    for (int off = 128; off > 0; off >>= 1) {
        if (tid < off) sh[tid] += sh[tid + off];
        __syncthreads();
    }
    if (tid == 0) g_partials[blockIdx.x] = sh[0];
}

__global__ void finalize_kernel() {
    __shared__ double sh[256];
    const int tid = threadIdx.x;
    double s = 0.0;
    for (int i = tid; i < NRED; i += 256) s += g_partials[i];
    sh[tid] = s;
    __syncthreads();
    for (int off = 128; off > 0; off >>= 1) {
        if (tid < off) sh[tid] += sh[tid + off];
        __syncthreads();
    }
    if (tid == 0) {
        double norm = sqrt(sh[0]);
        g_scale = (norm > 1.0) ? (float)(1.0 / norm) : 1.0f;
    }
}

__global__ void scale_kernel(float* __restrict__ W) {
    size_t i = (size_t)blockIdx.x * blockDim.x + threadIdx.x;
    const float s = g_scale;
    float4 v = ((float4*)W)[i];
    v.x *= s; v.y *= s; v.z *= s; v.w *= s;
    ((float4*)W)[i] = v;
}

// ---------------- launch ----------------
extern "C" void kernel_launch(void* const* d_in, const int* in_sizes, int n_in,
                              void* d_out, int out_size) {
    const float* x    = (const float*)d_in[0];  // [M, H]
    const float* pw   = (const float*)d_in[1];  // [H, H]
    const float* rate = (const float*)d_in[2];  // [1]
    const float* fw   = (const float*)d_in[3];  // [H, H]
    const float* fb   = (const float*)d_in[4];  // [H]
    const float* hs   = (const float*)d_in[5];  // scalar

    const int M = in_sizes[0] / HDIM;           // 16384
    float* combined = (float*)d_out;
    float* neww     = (float*)d_out + (size_t)M * HDIM;

    static bool attr_done = false;
    if (!attr_done) {
        cudaFuncSetAttribute(gemm1_mma, cudaFuncAttributeMaxDynamicSharedMemorySize, SMEM1);
        cudaFuncSetAttribute(gemm2_mma, cudaFuncAttributeMaxDynamicSharedMemorySize, SMEM2);
        attr_done = true;
    }

    __nv_bfloat16 *xhi, *xlo, *xthi, *xtlo, *whi, *wlo, *cthi;
    cudaGetSymbolAddress((void**)&xhi,  g_xhi);
    cudaGetSymbolAddress((void**)&xlo,  g_xlo);
    cudaGetSymbolAddress((void**)&xthi, g_xthi);
    cudaGetSymbolAddress((void**)&xtlo, g_xtlo);
    cudaGetSymbolAddress((void**)&whi,  g_whi);
    cudaGetSymbolAddress((void**)&wlo,  g_wlo);
    cudaGetSymbolAddress((void**)&cthi, g_cthi);

    // operand prep (split + transpose)
    wsplit_kernel<<<HDIM * HDIM / 4 / 256, 256>>>(fw, pw, whi, wlo);
    xsplit_kernel<<<(int)((size_t)M * HDIM / 4 / 256), 256>>>(x, xhi, xlo);
    {
        dim3 g(HDIM / 32, M / 32);
        tsplit_kernel<<<g, 256>>>(x, xthi, xtlo, M, HDIM);
    }

    // GEMM1
    {
        dim3 g(HDIM / BN, M / BM);
        gemm1_mma<<<g, 256, SMEM1>>>(fb, combined);
    }

    // transpose combined -> [H, M] (hi only; GEMM2 uses 2-product split)
    {
        dim3 g(HDIM / 32, M / 32);
        tsplit_hi_kernel<<<g, 256>>>(combined, cthi, M, HDIM);
    }

    // GEMM2 split-K partials, then deterministic combine
    {
        dim3 g(HDIM / BN, HDIM / BM, NSPLIT);
        gemm2_mma<<<g, 256, SMEM2>>>(M);
    }
    combine_kernel<<<HDIM * HDIM / 4 / 256, 256>>>(pw, rate, hs, neww, 1.0f / (float)M);

    sumsq_kernel<<<NRED, 256>>>(neww);
    finalize_kernel<<<1, 256>>>();
    scale_kernel<<<HDIM * HDIM / 4 / 256, 256>>>(neww);
}

// round 6
// speedup vs baseline: 4.2210x; 1.1723x over previous
#include <cuda_runtime.h>
#include <cuda_fp16.h>
#include <cstdint>

#define HDIM  2048
#define MROWS 16384
#define BM    128
#define BN    128
#define BK    64
#define NSPLIT 4
#define NRED  2048

#define TILE_BYTES  (128 * 128)        // 16KB: 128 rows x 128B (64 fp16)
#define STAGE3      (3 * TILE_BYTES)   // stage: Ahi Alo Bhi (48KB)
#define SMEM_DYN    (3 * STAGE3 + 1024)

// ---------------- device scratch (no allocs allowed) ----------------
__device__ __half g_xhi [(size_t)MROWS * HDIM];
__device__ __half g_xlo [(size_t)MROWS * HDIM];
__device__ __half g_xthi[(size_t)MROWS * HDIM];   // x^T [H, M]
__device__ __half g_xtlo[(size_t)MROWS * HDIM];
__device__ __half g_whi [(size_t)HDIM * HDIM];    // fp16(fw+pw)
__device__ __half g_cthi[(size_t)MROWS * HDIM];   // combined^T [H, M] (hi only)
__device__ float  g_part[(size_t)NSPLIT * HDIM * HDIM];  // split-K partials
__device__ double g_partials[NRED];
__device__ float  g_scale;

// ---------------- PTX helpers (baseline sm_80+ features only) ----------------
__device__ __forceinline__ uint32_t smem_u32(const void* p) {
    uint32_t a;
    asm("{ .reg .u64 t; cvta.to.shared.u64 t, %1; cvt.u32.u64 %0, t; }" : "=r"(a) : "l"(p));
    return a;
}
__device__ __forceinline__ uint32_t sw128(uint32_t o) { return o ^ ((o >> 3) & 0x70); }

__device__ __forceinline__ void cpasync16(uint32_t d, const void* s) {
    asm volatile("cp.async.cg.shared.global [%0], [%1], 16;" :: "r"(d), "l"(s));
}
#define CP_COMMIT() asm volatile("cp.async.commit_group;" ::: "memory")
#define CP_WAIT2()  asm volatile("cp.async.wait_group 2;" ::: "memory")
#define CP_WAIT1()  asm volatile("cp.async.wait_group 1;" ::: "memory")
#define CP_WAIT0()  asm volatile("cp.async.wait_group 0;" ::: "memory")

__device__ __forceinline__ void ldsm4(uint32_t* r, uint32_t addr) {
    asm volatile("ldmatrix.sync.aligned.m8n8.x4.shared.b16 {%0,%1,%2,%3}, [%4];"
                 : "=r"(r[0]), "=r"(r[1]), "=r"(r[2]), "=r"(r[3]) : "r"(addr));
}
__device__ __forceinline__ void mma16816(float* c, const uint32_t* a, const uint32_t* b) {
    asm volatile(
        "mma.sync.aligned.m16n8k16.row.col.f32.f16.f16.f32 "
        "{%0,%1,%2,%3}, {%4,%5,%6,%7}, {%8,%9}, {%0,%1,%2,%3};"
        : "+f"(c[0]), "+f"(c[1]), "+f"(c[2]), "+f"(c[3])
        : "r"(a[0]), "r"(a[1]), "r"(a[2]), "r"(a[3]), "r"(b[0]), "r"(b[1]));
}

// ---------------- split helpers ----------------
__device__ __forceinline__ void split1(float v, __half& h, __half& l) {
    h = __float2half(v);
    l = __float2half(v - __half2float(h));
}

__global__ void xsplit_kernel(const float* __restrict__ x,
                              __half* __restrict__ oh, __half* __restrict__ ol) {
    size_t i = (size_t)blockIdx.x * blockDim.x + threadIdx.x;   // float4 index
    float4 v = ((const float4*)x)[i];
    __half h0, h1, h2, h3, l0, l1, l2, l3;
    split1(v.x, h0, l0); split1(v.y, h1, l1); split1(v.z, h2, l2); split1(v.w, h3, l3);
    __half2* ph = (__half2*)oh + i * 2;
    __half2* pl = (__half2*)ol + i * 2;
    ph[0] = __halves2half2(h0, h1); ph[1] = __halves2half2(h2, h3);
    pl[0] = __halves2half2(l0, l1); pl[1] = __halves2half2(l2, l3);
}

__global__ void wsum_hi_kernel(const float* __restrict__ fw, const float* __restrict__ pw,
                               __half* __restrict__ oh) {
    size_t i = (size_t)blockIdx.x * blockDim.x + threadIdx.x;
    float4 a = ((const float4*)fw)[i];
    float4 b = ((const float4*)pw)[i];
    __half2* ph = (__half2*)oh + i * 2;
    ph[0] = __halves2half2(__float2half(a.x + b.x), __float2half(a.y + b.y));
    ph[1] = __halves2half2(__float2half(a.z + b.z), __float2half(a.w + b.w));
}

// in [R,C] fp32 -> out_hi/out_lo [C,R] fp16 (transpose + split)
__global__ void tsplit_kernel(const float* __restrict__ in,
                              __half* __restrict__ oh, __half* __restrict__ ol,
                              int R, int C) {
    __shared__ float t[32][33];
    int tid = threadIdx.x;                 // 256
    int r0 = blockIdx.y * 32, c0 = blockIdx.x * 32;
    int row = tid >> 3, seg = tid & 7;
    float4 v = *(const float4*)(in + (size_t)(r0 + row) * C + c0 + seg * 4);
    t[row][seg * 4 + 0] = v.x; t[row][seg * 4 + 1] = v.y;
    t[row][seg * 4 + 2] = v.z; t[row][seg * 4 + 3] = v.w;
    __syncthreads();
    int oc = row;
    int rs = seg * 4;
    float a0 = t[rs + 0][oc], a1 = t[rs + 1][oc], a2 = t[rs + 2][oc], a3 = t[rs + 3][oc];
    __half h0, h1, h2, h3, l0, l1, l2, l3;
    split1(a0, h0, l0); split1(a1, h1, l1); split1(a2, h2, l2); split1(a3, h3, l3);
    size_t ob = ((size_t)(c0 + oc) * R + r0 + rs) >> 1;
    __half2* ph = (__half2*)oh + ob;
    __half2* pl = (__half2*)ol + ob;
    ph[0] = __halves2half2(h0, h1); ph[1] = __halves2half2(h2, h3);
    pl[0] = __halves2half2(l0, l1); pl[1] = __halves2half2(l2, l3);
}

// transpose, hi only: in [R,C] fp32 -> out [C,R] fp16
__global__ void tsplit_hi_kernel(const float* __restrict__ in,
                                 __half* __restrict__ oh, int R, int C) {
    __shared__ float t[32][33];
    int tid = threadIdx.x;
    int r0 = blockIdx.y * 32, c0 = blockIdx.x * 32;
    int row = tid >> 3, seg = tid & 7;
    float4 v = *(const float4*)(in + (size_t)(r0 + row) * C + c0 + seg * 4);
    t[row][seg * 4 + 0] = v.x; t[row][seg * 4 + 1] = v.y;
    t[row][seg * 4 + 2] = v.z; t[row][seg * 4 + 3] = v.w;
    __syncthreads();
    int oc = row;
    int rs = seg * 4;
    __half h0 = __float2half(t[rs + 0][oc]);
    __half h1 = __float2half(t[rs + 1][oc]);
    __half h2 = __float2half(t[rs + 2][oc]);
    __half h3 = __float2half(t[rs + 3][oc]);
    size_t ob = ((size_t)(c0 + oc) * R + r0 + rs) >> 1;
    __half2* ph = (__half2*)oh + ob;
    ph[0] = __halves2half2(h0, h1); ph[1] = __halves2half2(h2, h3);
}

// ---------------- HMMA mainloop: fp16 2-product split, 3-stage pipeline -----
// D[m,n] = sum_k (Ahi+Alo)[m,k] * Bhi[n,k]   (stage = Ahi Alo Bhi)
__device__ __forceinline__ void mm_loop(float acc[4][4][4],
    const __half* __restrict__ Ahi, const __half* __restrict__ Alo,
    const __half* __restrict__ Bhi,
    int lda, int ldb, int m0, int n0, int kbeg, int NC)
{
    constexpr uint32_t A_HI = 0;
    constexpr uint32_t A_LO = TILE_BYTES;
    constexpr uint32_t B_HI = 2 * TILE_BYTES;

    extern __shared__ char dsm[];
    uint32_t raw = smem_u32(dsm);
    uint32_t sbase = (raw + 1023) & ~1023u;

    const int tid  = threadIdx.x;
    const int lane = tid & 31;
    const int wid  = tid >> 5;
    const int wm = (wid >> 2) * 64;
    const int wn = (wid & 3) * 32;

    const int arow  = wm + (lane & 15);
    const int akadd = (lane >> 4) << 3;
    const int nrow  = wn + (lane & 7) + ((lane >> 4) << 3);
    const int bkadd = ((lane >> 3) & 1) << 3;

    auto issue = [&](int c) {
        uint32_t sb = sbase + (uint32_t)(c % 3) * STAGE3;
        const int k0 = kbeg + c * BK;
        #pragma unroll
        for (int t = 0; t < 4; t++) {
            int seg = tid + t * 256;
            int r = seg >> 3, sc = seg & 7;
            uint32_t so = sw128((uint32_t)(r * 128 + sc * 16));
            size_t ga = (size_t)(m0 + r) * lda + k0 + sc * 8;
            size_t gb = (size_t)(n0 + r) * ldb + k0 + sc * 8;
            cpasync16(sb + A_HI + so, Ahi + ga);
            cpasync16(sb + A_LO + so, Alo + ga);
            cpasync16(sb + B_HI + so, Bhi + gb);
        }
    };

    issue(0); CP_COMMIT();
    issue(1); CP_COMMIT();

    #pragma unroll 1
    for (int c = 0; c < NC; c++) {
        if (c + 2 < NC) { issue(c + 2); CP_COMMIT(); CP_WAIT2(); }
        else if (c + 1 < NC) { CP_WAIT1(); }
        else { CP_WAIT0(); }
        __syncthreads();

        uint32_t st = sbase + (uint32_t)(c % 3) * STAGE3;
        #pragma unroll
        for (int ks = 0; ks < 4; ks++) {
            uint32_t ah[4][4], al[4][4], bh[4][2];
            #pragma unroll
            for (int mi = 0; mi < 4; mi++) {
                uint32_t off = sw128((uint32_t)((arow + mi * 16) * 128 + (ks * 16 + akadd) * 2));
                ldsm4(ah[mi], st + A_HI + off);
                ldsm4(al[mi], st + A_LO + off);
            }
            #pragma unroll
            for (int ng = 0; ng < 2; ng++) {
                uint32_t off = sw128((uint32_t)((nrow + ng * 16) * 128 + (ks * 16 + bkadd) * 2));
                uint32_t q[4];
                ldsm4(q, st + B_HI + off);
                bh[2*ng][0] = q[0]; bh[2*ng][1] = q[1];
                bh[2*ng+1][0] = q[2]; bh[2*ng+1][1] = q[3];
            }
            #pragma unroll
            for (int mi = 0; mi < 4; mi++)
                #pragma unroll
                for (int ni = 0; ni < 4; ni++) {
                    mma16816(acc[mi][ni], ah[mi], bh[ni]);
                    mma16816(acc[mi][ni], al[mi], bh[ni]);
                }
        }
        __syncthreads();
    }
}

// ---------------- GEMM1: combined = x @ Wsum^T + bias ----------------
__global__ __launch_bounds__(256, 1)
void gemm1_mma(const float* __restrict__ bias, float* __restrict__ Cout) {
    float acc[4][4][4];
    #pragma unroll
    for (int i = 0; i < 4; i++)
        #pragma unroll
        for (int j = 0; j < 4; j++)
            #pragma unroll
            for (int q = 0; q < 4; q++) acc[i][j][q] = 0.f;

    const int m0 = blockIdx.y * BM, n0 = blockIdx.x * BN;
    mm_loop(acc, g_xhi, g_xlo, g_whi, HDIM, HDIM, m0, n0, 0, HDIM / BK);

    const int lane = threadIdx.x & 31, wid = threadIdx.x >> 5;
    const int wm = (wid >> 2) * 64, wn = (wid & 3) * 32;
    const int rbase = m0 + wm + (lane >> 2);
    const int cbase = n0 + wn + (lane & 3) * 2;
    #pragma unroll
    for (int mi = 0; mi < 4; mi++)
        #pragma unroll
        for (int ni = 0; ni < 4; ni++) {
            int r = rbase + mi * 16, cc = cbase + ni * 8;
            float2 bv = *(const float2*)(bias + cc);
            *(float2*)(Cout + (size_t)r * HDIM + cc) =
                make_float2(acc[mi][ni][0] + bv.x, acc[mi][ni][1] + bv.y);
            *(float2*)(Cout + (size_t)(r + 8) * HDIM + cc) =
                make_float2(acc[mi][ni][2] + bv.x, acc[mi][ni][3] + bv.y);
        }
}

// ---------------- GEMM2 partial: P[s] = X^T @ C over k-split s ----------------
__global__ __launch_bounds__(256, 1)
void gemm2_mma(int M) {
    float acc[4][4][4];
    #pragma unroll
    for (int i = 0; i < 4; i++)
        #pragma unroll
        for (int j = 0; j < 4; j++)
            #pragma unroll
            for (int q = 0; q < 4; q++) acc[i][j][q] = 0.f;

    const int s = blockIdx.z;
    const int kper = M / NSPLIT;
    const int h0 = blockIdx.y * BM, n0 = blockIdx.x * BN;
    mm_loop(acc, g_xthi, g_xtlo, g_cthi, M, M, h0, n0, s * kper, kper / BK);

    float* P = g_part + (size_t)s * HDIM * HDIM;
    const int lane = threadIdx.x & 31, wid = threadIdx.x >> 5;
    const int wm = (wid >> 2) * 64, wn = (wid & 3) * 32;
    const int rbase = h0 + wm + (lane >> 2);
    const int cbase = n0 + wn + (lane & 3) * 2;
    #pragma unroll
    for (int mi = 0; mi < 4; mi++)
        #pragma unroll
        for (int ni = 0; ni < 4; ni++) {
            int r = rbase + mi * 16, cc = cbase + ni * 8;
            *(float2*)(P + (size_t)r * HDIM + cc) =
                make_float2(acc[mi][ni][0], acc[mi][ni][1]);
            *(float2*)(P + (size_t)(r + 8) * HDIM + cc) =
                make_float2(acc[mi][ni][2], acc[mi][ni][3]);
        }
}

// ---------------- combine + norm + scale ----------------
__global__ void combine_kernel(const float* __restrict__ plastic,
                               const float* __restrict__ rate,
                               const float* __restrict__ hs,
                               float* __restrict__ Wout, float invM) {
    size_t i = (size_t)blockIdx.x * blockDim.x + threadIdx.x;   // float4 index
    const float factor = rate[0] * hs[0] * invM;
    const size_t stride4 = (size_t)HDIM * HDIM / 4;
    float4 s0 = ((const float4*)g_part)[i];
    float4 s1 = ((const float4*)g_part)[i + stride4];
    float4 s2 = ((const float4*)g_part)[i + 2 * stride4];
    float4 s3 = ((const float4*)g_part)[i + 3 * stride4];
    float4 p  = ((const float4*)plastic)[i];
    float4 o;
    o.x = p.x + factor * (s0.x + s1.x + s2.x + s3.x);
    o.y = p.y + factor * (s0.y + s1.y + s2.y + s3.y);
    o.z = p.z + factor * (s0.z + s1.z + s2.z + s3.z);
    o.w = p.w + factor * (s0.w + s1.w + s2.w + s3.w);
    ((float4*)Wout)[i] = o;
}

__global__ void sumsq_kernel(const float* __restrict__ W) {
    __shared__ double sh[256];
    const int tid = threadIdx.x;
    const float4* W4 = (const float4*)W;
    const size_t total4 = (size_t)HDIM * HDIM / 4;
    double s = 0.0;
    for (size_t i = (size_t)blockIdx.x * 256 + tid; i < total4;
         i += (size_t)gridDim.x * 256) {
        float4 v = W4[i];
        s += (double)v.x * v.x + (double)v.y * v.y
           + (double)v.z * v.z + (double)v.w * v.w;
    }
    sh[tid] = s;
    __syncthreads();
    for (int off = 128; off > 0; off >>= 1) {
        if (tid < off) sh[tid] += sh[tid + off];
        __syncthreads();
    }
    if (tid == 0) g_partials[blockIdx.x] = sh[0];
}

__global__ void finalize_kernel() {
    __shared__ double sh[256];
    const int tid = threadIdx.x;
    double s = 0.0;
    for (int i = tid; i < NRED; i += 256) s += g_partials[i];
    sh[tid] = s;
    __syncthreads();
    for (int off = 128; off > 0; off >>= 1) {
        if (tid < off) sh[tid] += sh[tid + off];
        __syncthreads();
    }
    if (tid == 0) {
        double norm = sqrt(sh[0]);
        g_scale = (norm > 1.0) ? (float)(1.0 / norm) : 1.0f;
    }
}

__global__ void scale_kernel(float* __restrict__ W) {
    size_t i = (size_t)blockIdx.x * blockDim.x + threadIdx.x;
    const float s = g_scale;
    float4 v = ((float4*)W)[i];
    v.x *= s; v.y *= s; v.z *= s; v.w *= s;
    ((float4*)W)[i] = v;
}

// ---------------- launch ----------------
extern "C" void kernel_launch(void* const* d_in, const int* in_sizes, int n_in,
                              void* d_out, int out_size) {
    const float* x    = (const float*)d_in[0];  // [M, H]
    const float* pw   = (const float*)d_in[1];  // [H, H]
    const float* rate = (const float*)d_in[2];  // [1]
    const float* fw   = (const float*)d_in[3];  // [H, H]
    const float* fb   = (const float*)d_in[4];  // [H]
    const float* hs   = (const float*)d_in[5];  // scalar

    const int M = in_sizes[0] / HDIM;           // 16384
    float* combined = (float*)d_out;
    float* neww     = (float*)d_out + (size_t)M * HDIM;

    static bool attr_done = false;
    if (!attr_done) {
        cudaFuncSetAttribute(gemm1_mma, cudaFuncAttributeMaxDynamicSharedMemorySize, SMEM_DYN);
        cudaFuncSetAttribute(gemm2_mma, cudaFuncAttributeMaxDynamicSharedMemorySize, SMEM_DYN);
        attr_done = true;
    }

    __half *xhi, *xlo, *xthi, *xtlo, *whi, *cthi;
    cudaGetSymbolAddress((void**)&xhi,  g_xhi);
    cudaGetSymbolAddress((void**)&xlo,  g_xlo);
    cudaGetSymbolAddress((void**)&xthi, g_xthi);
    cudaGetSymbolAddress((void**)&xtlo, g_xtlo);
    cudaGetSymbolAddress((void**)&whi,  g_whi);
    cudaGetSymbolAddress((void**)&cthi, g_cthi);

    // operand prep (split + transpose)
    wsum_hi_kernel<<<HDIM * HDIM / 4 / 256, 256>>>(fw, pw, whi);
    xsplit_kernel<<<(int)((size_t)M * HDIM / 4 / 256), 256>>>(x, xhi, xlo);
    {
        dim3 g(HDIM / 32, M / 32);
        tsplit_kernel<<<g, 256>>>(x, xthi, xtlo, M, HDIM);
    }

    // GEMM1
    {
        dim3 g(HDIM / BN, M / BM);
        gemm1_mma<<<g, 256, SMEM_DYN>>>(fb, combined);
    }

    // transpose combined -> [H, M] (hi only)
    {
        dim3 g(HDIM / 32, M / 32);
        tsplit_hi_kernel<<<g, 256>>>(combined, cthi, M, HDIM);
    }

    // GEMM2 split-K partials, then deterministic combine
    {
        dim3 g(HDIM / BN, HDIM / BM, NSPLIT);
        gemm2_mma<<<g, 256, SMEM_DYN>>>(M);
    }
    combine_kernel<<<HDIM * HDIM / 4 / 256, 256>>>(pw, rate, hs, neww, 1.0f / (float)M);

    sumsq_kernel<<<NRED, 256>>>(neww);
    finalize_kernel<<<1, 256>>>();
    scale_kernel<<<HDIM * HDIM / 4 / 256, 256>>>(neww);
}